// round 5
// baseline (speedup 1.0000x reference)
#include <cuda_runtime.h>
#include <cstdint>

#define Tn 512
#define Bn 128
#define Hn 256
#define Gn 1024
#define NBLK 128

typedef unsigned long long u64t;

// ---------------- device scratch ----------------
__device__ float g_pre0[(size_t)Tn * Gn * Bn];   // [t][gatecol][b]
__device__ float g_h0[2][Hn * Bn];               // [pp][h][b]
__device__ float g_h1[2][Hn * Bn];
__device__ volatile unsigned g_bar_gen = 0;
__device__ unsigned g_bar_cnt = 0;

__device__ __forceinline__ float fsig(float x) {
    return __fdividef(1.0f, 1.0f + __expf(-x));
}
__device__ __forceinline__ float ftanh2(float x) {
    float e = __expf(2.0f * x);
    return 1.0f - __fdividef(2.0f, e + 1.0f);
}
__device__ __forceinline__ void grid_barrier() {
    __syncthreads();
    if (threadIdx.x == 0) {
        unsigned gen = g_bar_gen;
        __threadfence();
        if (atomicAdd(&g_bar_cnt, 1u) == (unsigned)(NBLK - 1)) {
            g_bar_cnt = 0u;
            __threadfence();
            g_bar_gen = gen + 1u;
        } else {
            while (g_bar_gen == gen) {}
            __threadfence();
        }
    }
    __syncthreads();
}

__device__ __forceinline__ void ffma2(u64t& d, u64t a, u64t b) {
    asm volatile("fma.rn.f32x2 %0, %1, %2, %0;" : "+l"(d) : "l"(a), "l"(b));
}
__device__ __forceinline__ u64t dup2(float w) {
    u64t r;
    asm("mov.b64 %0, {%1, %1};" : "=l"(r) : "f"(w));
    return r;
}
__device__ __forceinline__ u64t pack2(float a, float b) {
    u64t r;
    asm("mov.b64 %0, {%1, %2};" : "=l"(r) : "f"(a), "f"(b));
    return r;
}
__device__ __forceinline__ float2 unpack2(u64t v) {
    float2 r;
    asm("mov.b64 {%0, %1}, %2;" : "=f"(r.x), "=f"(r.y) : "l"(v));
    return r;
}
__device__ __forceinline__ u64t addx2(u64t a, u64t b) {
    u64t r;
    asm("add.rn.f32x2 %0, %1, %2;" : "=l"(r) : "l"(a), "l"(b));
    return r;
}
__device__ __forceinline__ void cp16(float* dst, const float* src) {
    unsigned d = (unsigned)__cvta_generic_to_shared(dst);
    asm volatile("cp.async.cg.shared.global [%0], [%1], 16;" :: "r"(d), "l"(src));
}

// ---------------------------------------------------------------------------
// Precompute: pre0[t][g][b] = b_ih0[g]+b_hh0[g] + sum_k x[t][b][k]*W_ih0[g][k]
// Tile 128g x 64b, 256 threads, thread = 8g x 4b (2 pairs). FFMA2 throughout.
// grid = (8 gt, 2 bt, 512 t)
// ---------------------------------------------------------------------------
__global__ __launch_bounds__(256) void precompute_kernel(
    const float* __restrict__ x, const float* __restrict__ W_ih,
    const float* __restrict__ b_ih, const float* __restrict__ b_hh)
{
    __shared__ __align__(16) u64t Xs[32][34];    // [k][bpair]
    __shared__ __align__(16) u64t Ws[32][130];   // [k][g] dup'd
    const int gt = blockIdx.x;
    const int bt = blockIdx.y;
    const int t  = blockIdx.z;
    const int tid = threadIdx.x;
    const int gy = tid >> 4;      // 0..15 -> 8 g each
    const int bx = tid & 15;      // 0..15 -> 2 pairs (4 batch)

    const float* xb = x + ((size_t)t * Bn + bt * 64) * Hn;
    const float* wb = W_ih + (size_t)(gt * 128) * Hn;

    u64t acc[8][2];
#pragma unroll
    for (int i = 0; i < 8; i++) { acc[i][0] = 0ull; acc[i][1] = 0ull; }

    for (int kc = 0; kc < Hn; kc += 32) {
        {   // Xs: pack batch pairs (32 pairs x 32 k)
            int bp = tid & 31;
            int k4 = (tid >> 5) * 4;
            const float* r0 = xb + (size_t)(2 * bp) * Hn + kc + k4;
            float4 a = *reinterpret_cast<const float4*>(r0);
            float4 b4 = *reinterpret_cast<const float4*>(r0 + Hn);
            Xs[k4 + 0][bp] = pack2(a.x, b4.x);
            Xs[k4 + 1][bp] = pack2(a.y, b4.y);
            Xs[k4 + 2][bp] = pack2(a.z, b4.z);
            Xs[k4 + 3][bp] = pack2(a.w, b4.w);
        }
#pragma unroll
        for (int j = 0; j < 4; j++) {  // Ws: 128 g x 32 k dup'd
            int s = tid + j * 256;
            int g = s & 127;
            int k4 = (s >> 7) * 4;
            float4 w = *reinterpret_cast<const float4*>(wb + (size_t)g * Hn + kc + k4);
            Ws[k4 + 0][g] = dup2(w.x);
            Ws[k4 + 1][g] = dup2(w.y);
            Ws[k4 + 2][g] = dup2(w.z);
            Ws[k4 + 3][g] = dup2(w.w);
        }
        __syncthreads();
#pragma unroll
        for (int kk = 0; kk < 32; kk++) {
            ulonglong2 hv = *reinterpret_cast<const ulonglong2*>(&Xs[kk][bx * 2]);
            ulonglong2 w01 = *reinterpret_cast<const ulonglong2*>(&Ws[kk][gy * 8]);
            ulonglong2 w23 = *reinterpret_cast<const ulonglong2*>(&Ws[kk][gy * 8 + 2]);
            ulonglong2 w45 = *reinterpret_cast<const ulonglong2*>(&Ws[kk][gy * 8 + 4]);
            ulonglong2 w67 = *reinterpret_cast<const ulonglong2*>(&Ws[kk][gy * 8 + 6]);
            ffma2(acc[0][0], hv.x, w01.x); ffma2(acc[0][1], hv.y, w01.x);
            ffma2(acc[1][0], hv.x, w01.y); ffma2(acc[1][1], hv.y, w01.y);
            ffma2(acc[2][0], hv.x, w23.x); ffma2(acc[2][1], hv.y, w23.x);
            ffma2(acc[3][0], hv.x, w23.y); ffma2(acc[3][1], hv.y, w23.y);
            ffma2(acc[4][0], hv.x, w45.x); ffma2(acc[4][1], hv.y, w45.x);
            ffma2(acc[5][0], hv.x, w45.y); ffma2(acc[5][1], hv.y, w45.y);
            ffma2(acc[6][0], hv.x, w67.x); ffma2(acc[6][1], hv.y, w67.x);
            ffma2(acc[7][0], hv.x, w67.y); ffma2(acc[7][1], hv.y, w67.y);
        }
        __syncthreads();
    }
#pragma unroll
    for (int gi = 0; gi < 8; gi++) {
        int g = gt * 128 + gy * 8 + gi;
        float bias = __ldg(b_ih + g) + __ldg(b_hh + g);
        float2 lo = unpack2(acc[gi][0]);
        float2 hi = unpack2(acc[gi][1]);
        float4 v = make_float4(lo.x + bias, lo.y + bias, hi.x + bias, hi.y + bias);
        *reinterpret_cast<float4*>(g_pre0 + (size_t)t * (Gn * Bn)
            + (size_t)g * Bn + bt * 64 + bx * 4) = v;
    }
}

// ---------------------------------------------------------------------------
// Persistent skewed recurrence. 128 CTAs x 512 threads (16 warps).
// CTA(blk): bh=blk&1 (batch half), cg=blk>>1 (4 h-cols of both layers).
// Warp w: bs = w&7 (8-batch slice), kshi = w>>3 (128-K slice).
// Lane: cs = lane&15 (gate col), kslo = lane>>4 (64-K sub-slice).
// Warp-private cp.async staging -> NO block syncs inside GEMM.
// ---------------------------------------------------------------------------
#define SM_WHH0 0          // u64 dup [256][16] : 32768
#define SM_WIH1 32768      // float   [256][16] : 16384
#define SM_WHH1 49152      // float   [256][16] : 16384
#define SM_HST  65536      // 16 warps x 2 slices x 128 rows x 8 floats : 131072
#define SM_PART 196608     // float[64][76] : 19456
#define SMEM_TOTAL 216064

__global__ __launch_bounds__(512, 1) void lstm_persistent(
    const float* __restrict__ W_ih, const float* __restrict__ W_hh,
    const float* __restrict__ b_ih, const float* __restrict__ b_hh,
    float* __restrict__ out)
{
    extern __shared__ __align__(16) char smraw[];
    u64t*  Whh0 = reinterpret_cast<u64t*>(smraw + SM_WHH0);
    float* Wih1 = reinterpret_cast<float*>(smraw + SM_WIH1);
    float* Whh1 = reinterpret_cast<float*>(smraw + SM_WHH1);
    float* Hst  = reinterpret_cast<float*>(smraw + SM_HST);
    float* part = reinterpret_cast<float*>(smraw + SM_PART);

    const int tid = threadIdx.x;
    const int blk = blockIdx.x;
    const int bh = blk & 1;
    const int cg = blk >> 1;
    const int w = tid >> 5;
    const int lane = tid & 31;
    const int bs = w & 7;
    const int kshi = w >> 3;          // 0..1
    const int cs = lane & 15;
    const int kslo = lane >> 4;       // 0..1

    // ---- weights into smem (once) ----
    {
        const int wcs = tid & 15;
        const int kg = tid >> 4;      // 0..31
        const int gc = (wcs >> 2) * Hn + cg * 4 + (wcs & 3);
        const float* wh0 = W_hh + (size_t)gc * Hn;
        const float* wi1 = W_ih + (size_t)Gn * Hn + (size_t)gc * Hn;
        const float* wh1 = W_hh + (size_t)Gn * Hn + (size_t)gc * Hn;
#pragma unroll
        for (int j = 0; j < 8; j++) {
            int k = kg * 8 + j;
            Whh0[k * 16 + wcs] = dup2(__ldg(wh0 + k));
            Wih1[k * 16 + wcs] = __ldg(wi1 + k);
            Whh1[k * 16 + wcs] = __ldg(wh1 + k);
        }
    }
    // elementwise identity
    const int lay = tid >> 8;
    const int hcl = (tid >> 6) & 3;
    const int bl  = tid & 63;
    const int hcol = cg * 4 + hcl;
    const int b = bh * 64 + bl;
    float b1s[4];
#pragma unroll
    for (int g = 0; g < 4; g++)
        b1s[g] = __ldg(b_ih + Gn + g * Hn + hcol) + __ldg(b_hh + Gn + g * Hn + hcol);

    // staging constants (per lane)
    float* myStA = Hst + w * 2048;
    float* myStB = myStA + 1024;
    const int r0 = lane >> 1;                 // + j*16
    const int co = (lane & 1) * 4;            // float offset within row
    const size_t srcBase = (size_t)(kshi * 128) * Bn + bh * 64 + bs * 8 + co;
    const float* HA = myStA + kslo * 512;
    const float* HB = myStB + kslo * 512;

    // zero init h ping-pong buffers
    {
        int idx = blk * 512 + tid;
        reinterpret_cast<float*>(g_h0)[idx] = 0.f;
        reinterpret_cast<float*>(g_h1)[idx] = 0.f;
    }
    float creg = 0.f;

    const size_t OUT_H = (size_t)Tn * Bn * Hn;
    const size_t OUT_C = OUT_H + 2 * (size_t)Bn * Hn;

    grid_barrier();

    for (int i = 0; i <= Tn; i++) {
        const int rslot = (i & 1) ^ 1;
        const int wslot = i & 1;
        const float* hA = g_h0[rslot];
        const float* hB = g_h1[rslot];

        // prefetch pre0 gate values (L0 elementwise operand)
        float pg[4] = {0.f, 0.f, 0.f, 0.f};
        if (lay == 0 && i < Tn) {
            const float* pb = g_pre0 + (size_t)i * (Gn * Bn);
#pragma unroll
            for (int g = 0; g < 4; g++)
                pg[g] = __ldg(pb + (size_t)(g * Hn + hcol) * Bn + b);
        }

        // ---- warp-private staging: slice A (h0), slice B (h1) ----
#pragma unroll
        for (int j = 0; j < 8; j++) {
            int r = r0 + j * 16;
            cp16(myStA + r * 8 + co, hA + srcBase + (size_t)r * Bn);
        }
        asm volatile("cp.async.commit_group;");
#pragma unroll
        for (int j = 0; j < 8; j++) {
            int r = r0 + j * 16;
            cp16(myStB + r * 8 + co, hB + srcBase + (size_t)r * Bn);
        }
        asm volatile("cp.async.commit_group;");

        u64t aL0[4], aL1[4], aR[4];
#pragma unroll
        for (int p = 0; p < 4; p++) { aL0[p] = 0ull; aL1[p] = 0ull; aR[p] = 0ull; }

        asm volatile("cp.async.wait_group 1;");
        __syncwarp();
        // ---- phase A: L0 recurrent + L1 input-proj on h0 slice ----
        {
            const int gkb = (kshi * 128 + kslo * 64) * 16 + cs;
#pragma unroll 8
            for (int u = 0; u < 64; u++) {
                ulonglong2 h01 = *reinterpret_cast<const ulonglong2*>(HA + u * 8);
                ulonglong2 h23 = *reinterpret_cast<const ulonglong2*>(HA + u * 8 + 4);
                u64t w0 = Whh0[gkb + u * 16];
                u64t w1 = dup2(Wih1[gkb + u * 16]);
                ffma2(aL0[0], h01.x, w0); ffma2(aL0[1], h01.y, w0);
                ffma2(aL0[2], h23.x, w0); ffma2(aL0[3], h23.y, w0);
                ffma2(aL1[0], h01.x, w1); ffma2(aL1[1], h01.y, w1);
                ffma2(aL1[2], h23.x, w1); ffma2(aL1[3], h23.y, w1);
            }
        }
        asm volatile("cp.async.wait_group 0;");
        __syncwarp();
        // ---- phase B: L1 recurrent on h1 slice ----
        {
            const int gkb = (kshi * 128 + kslo * 64) * 16 + cs;
#pragma unroll 8
            for (int u = 0; u < 64; u++) {
                ulonglong2 h01 = *reinterpret_cast<const ulonglong2*>(HB + u * 8);
                ulonglong2 h23 = *reinterpret_cast<const ulonglong2*>(HB + u * 8 + 4);
                u64t w2 = dup2(Whh1[gkb + u * 16]);
                ffma2(aR[0], h01.x, w2); ffma2(aR[1], h01.y, w2);
                ffma2(aR[2], h23.x, w2); ffma2(aR[3], h23.y, w2);
            }
        }
        // ---- in-warp reduce over kslo, combine L1 parts ----
#pragma unroll
        for (int p = 0; p < 4; p++) {
            aL1[p] = addx2(aL1[p], aR[p]);
            aL0[p] = addx2(aL0[p], (u64t)__shfl_xor_sync(0xFFFFFFFFu, aL0[p], 16));
            aL1[p] = addx2(aL1[p], (u64t)__shfl_xor_sync(0xFFFFFFFFu, aL1[p], 16));
        }
        if (kslo == 0) {
            float* p0 = part + (cs * 2 + kshi) * 76 + bs * 8;
            reinterpret_cast<ulonglong2*>(p0)[0] = make_ulonglong2(aL0[0], aL0[1]);
            reinterpret_cast<ulonglong2*>(p0)[1] = make_ulonglong2(aL0[2], aL0[3]);
            float* p1 = part + ((16 + cs) * 2 + kshi) * 76 + bs * 8;
            reinterpret_cast<ulonglong2*>(p1)[0] = make_ulonglong2(aL1[0], aL1[1]);
            reinterpret_cast<ulonglong2*>(p1)[1] = make_ulonglong2(aL1[2], aL1[3]);
        }
        __syncthreads();

        // ---- elementwise: lay0 -> L0 step i, lay1 -> L1 step i-1 ----
        if (lay == 0) {
            if (i < Tn) {
                float s[4];
#pragma unroll
                for (int g = 0; g < 4; g++) {
                    const float* pr = part + ((g * 4 + hcl) * 2) * 76 + bl;
                    s[g] = pg[g] + pr[0] + pr[76];
                }
                float cn = fsig(s[1]) * creg + fsig(s[0]) * ftanh2(s[2]);
                creg = cn;
                float hn = fsig(s[3]) * ftanh2(cn);
                g_h0[wslot][hcol * Bn + b] = hn;
                if (i == Tn - 1) {
                    out[OUT_H + (size_t)b * Hn + hcol] = hn;
                    out[OUT_C + (size_t)b * Hn + hcol] = cn;
                }
            }
        } else {
            if (i >= 1) {
                const int t1 = i - 1;
                float s[4];
#pragma unroll
                for (int g = 0; g < 4; g++) {
                    const float* pr = part + ((16 + g * 4 + hcl) * 2) * 76 + bl;
                    s[g] = b1s[g] + pr[0] + pr[76];
                }
                float cn = fsig(s[1]) * creg + fsig(s[0]) * ftanh2(s[2]);
                creg = cn;
                float hn = fsig(s[3]) * ftanh2(cn);
                g_h1[wslot][hcol * Bn + b] = hn;
                out[(size_t)t1 * (Bn * Hn) + (size_t)b * Hn + hcol] = hn;
                if (i == Tn) {
                    out[OUT_H + (size_t)Bn * Hn + (size_t)b * Hn + hcol] = hn;
                    out[OUT_C + (size_t)Bn * Hn + (size_t)b * Hn + hcol] = cn;
                }
            }
        }
        grid_barrier();
    }
}

extern "C" void kernel_launch(void* const* d_in, const int* in_sizes, int n_in,
                              void* d_out, int out_size) {
    (void)in_sizes; (void)n_in; (void)out_size;
    const float* x    = (const float*)d_in[0];
    const float* W_ih = (const float*)d_in[1];
    const float* W_hh = (const float*)d_in[2];
    const float* b_ih = (const float*)d_in[3];
    const float* b_hh = (const float*)d_in[4];
    float* out = (float*)d_out;

    cudaFuncSetAttribute(lstm_persistent,
                         cudaFuncAttributeMaxDynamicSharedMemorySize, SMEM_TOTAL);

    dim3 gPre(8, 2, 512);
    precompute_kernel<<<gPre, 256>>>(x, W_ih, b_ih, b_hh);
    lstm_persistent<<<NBLK, 512, SMEM_TOTAL>>>(W_ih, W_hh, b_ih, b_hh, out);
}